// round 2
// baseline (speedup 1.0000x reference)
#include <cuda_runtime.h>

// ---------------------------------------------------------------------------
// MeanPooling: out[b,:] = mean of x[i,:] over rows i with batch[i]==b
// x: (N,128) fp32, batch: (N,) sorted int64-or-int32, out: (4096,128) fp32
// Strategy: warp-per-row-range segmented reduction exploiting sorted batch.
// ---------------------------------------------------------------------------

#define D 128
#define MAXB 8192
#define MAXN (1 << 21)

__device__ int g_batch32[MAXN];   // converted batch indices (int32)
__device__ int g_counts[MAXB];    // per-segment row counts
__device__ int g_is64;            // 1 if batch input is int64, 0 if int32

// Detect dtype of batch buffer. Reads only within the first n 32-bit words,
// which is in-bounds for both int32 (n words) and int64 (2n words) layouts.
// For int64 little-endian, odd words are high halves == 0 (values < 4096).
// For int32 sorted-random data, the tail words are ~num_graphs-1 (nonzero).
__global__ void k_detect(const unsigned int* __restrict__ words, int n) {
    if (threadIdx.x == 0) {
        int top = n - 1;
        if ((top & 1) == 0) top--;          // largest odd index <= n-1
        int nz = 0;
        for (int k = 0; k < 32; k++) {
            int idx = top - 2 * k;
            if (idx < 1) break;
            if (words[idx] != 0u) { nz = 1; break; }
        }
        g_is64 = (nz == 0) ? 1 : 0;
    }
}

__global__ void k_convert(const void* __restrict__ batch, int n) {
    int i = blockIdx.x * blockDim.x + threadIdx.x;
    if (i >= n) return;
    if (g_is64) {
        g_batch32[i] = (int)((const long long*)batch)[i];
    } else {
        g_batch32[i] = ((const int*)batch)[i];
    }
}

__global__ void k_zero(float* __restrict__ out, int out_size, int nb) {
    int i = blockIdx.x * blockDim.x + threadIdx.x;
    if (i < out_size) out[i] = 0.0f;
    if (i < nb) g_counts[i] = 0;
}

__device__ __forceinline__ void flush_seg(float* __restrict__ out, int seg,
                                          int lane, const float4& acc, int cnt) {
    float* p = out + (size_t)seg * D + lane * 4;
    atomicAdd(p + 0, acc.x);
    atomicAdd(p + 1, acc.y);
    atomicAdd(p + 2, acc.z);
    atomicAdd(p + 3, acc.w);
    if (lane == 0) atomicAdd(&g_counts[seg], cnt);
}

__global__ void __launch_bounds__(256, 4) k_accum(const float4* __restrict__ x4,
                                                  float* __restrict__ out, int n) {
    const int lane = threadIdx.x & 31;
    const int wid = (blockIdx.x << 3) + (threadIdx.x >> 5);
    const int tw = gridDim.x << 3;
    const int per = (n + tw - 1) / tw;
    int r0 = wid * per;
    int r1 = min(r0 + per, n);
    if (r0 >= r1) return;

    float4 acc = make_float4(0.f, 0.f, 0.f, 0.f);
    int cur = g_batch32[r0];
    int cnt = 0;

    int r = r0;
    // Main chunked loop: 8 rows per iteration. All 8 float4 loads are issued
    // before the branch so the warp keeps 8+ loads in flight (DRAM MLP).
    for (; r + 8 <= r1; r += 8) {
        float4 v[8];
#pragma unroll
        for (int k = 0; k < 8; k++)
            v[k] = x4[(size_t)(r + k) * 32 + lane];
        int blast = g_batch32[r + 7];
        if (blast == cur) {
            // sorted + last==cur  =>  whole chunk belongs to cur segment
#pragma unroll
            for (int k = 0; k < 8; k++) {
                acc.x += v[k].x; acc.y += v[k].y;
                acc.z += v[k].z; acc.w += v[k].w;
            }
            cnt += 8;
        } else {
#pragma unroll
            for (int k = 0; k < 8; k++) {
                int b = g_batch32[r + k];
                if (b != cur) {
                    flush_seg(out, cur, lane, acc, cnt);
                    acc = make_float4(0.f, 0.f, 0.f, 0.f);
                    cnt = 0;
                    cur = b;
                }
                acc.x += v[k].x; acc.y += v[k].y;
                acc.z += v[k].z; acc.w += v[k].w;
                cnt++;
            }
        }
    }
    // Tail rows
    for (; r < r1; r++) {
        int b = g_batch32[r];
        if (b != cur) {
            flush_seg(out, cur, lane, acc, cnt);
            acc = make_float4(0.f, 0.f, 0.f, 0.f);
            cnt = 0;
            cur = b;
        }
        float4 v = x4[(size_t)r * 32 + lane];
        acc.x += v.x; acc.y += v.y; acc.z += v.z; acc.w += v.w;
        cnt++;
    }
    flush_seg(out, cur, lane, acc, cnt);
}

__global__ void k_div(float* __restrict__ out, int out_size) {
    int i = blockIdx.x * blockDim.x + threadIdx.x;
    if (i >= out_size) return;
    int seg = i >> 7;  // / D
    float c = (float)g_counts[seg];
    out[i] = out[i] / fmaxf(c, 1.0f);
}

extern "C" void kernel_launch(void* const* d_in, const int* in_sizes, int n_in,
                              void* d_out, int out_size) {
    const float* x = (const float*)d_in[0];
    const void* batch = d_in[1];

    int n = in_sizes[0] / D;               // number of rows
    if (n > MAXN) n = MAXN;                // safety clamp (fixed N=2^20 here)
    int nb = out_size / D;                 // number of segments
    if (nb > MAXB) nb = MAXB;
    float* out = (float*)d_out;

    // 1) detect batch dtype (int64 vs int32)
    k_detect<<<1, 32>>>((const unsigned int*)batch, n);
    // 2) convert batch -> int32 scratch
    k_convert<<<(n + 255) / 256, 256>>>(batch, n);
    // 3) zero output + counts
    int zmax = out_size > nb ? out_size : nb;
    k_zero<<<(zmax + 255) / 256, 256>>>(out, out_size, nb);
    // 4) segmented sum (warp-per-range, sorted fast path)
    k_accum<<<512, 256>>>((const float4*)x, out, n);
    // 5) divide by counts
    k_div<<<(out_size + 255) / 256, 256>>>(out, out_size);
}

// round 3
// speedup vs baseline: 1.1535x; 1.1535x over previous
#include <cuda_runtime.h>

// ---------------------------------------------------------------------------
// MeanPooling: out[b,:] = mean of x[i,:] over rows i with batch[i]==b
// x: (N,128) fp32, batch: (N,) sorted int64-or-int32, out: (4096,128) fp32
// R2: 3 graph nodes (prep, accum, div). accum reads batch directly (no
// conversion pass), 4-row chunks for lower reg pressure -> higher occupancy.
// ---------------------------------------------------------------------------

#define D 128
#define MAXB 8192

__device__ int g_counts[MAXB];    // per-segment row counts
__device__ int g_is64;            // 1 if batch input is int64, 0 if int32

// prep: zero out + counts, and detect batch dtype (thread 0 of block 0).
// Dtype detect reads only the first n 32-bit words (in-bounds for both
// layouts). int64 little-endian: odd words are high halves == 0 (vals<4096).
// int32 sorted data: tail words ~ num_graphs-1 (nonzero).
__global__ void k_prep(float* __restrict__ out, int out_size, int nb,
                       const unsigned int* __restrict__ bwords, int n) {
    int i = blockIdx.x * blockDim.x + threadIdx.x;
    if (i < out_size) out[i] = 0.0f;
    if (i < nb) g_counts[i] = 0;
    if (i == 0) {
        int top = n - 1;
        if ((top & 1) == 0) top--;          // largest odd index <= n-1
        int nz = 0;
        for (int k = 0; k < 32; k++) {
            int idx = top - 2 * k;
            if (idx < 1) break;
            if (bwords[idx] != 0u) { nz = 1; break; }
        }
        g_is64 = (nz == 0) ? 1 : 0;
    }
}

struct BatchReader {
    const int* b32;
    const int* b64;   // viewed as int pairs; low word at 2*i
    int is64;
    __device__ __forceinline__ int get(int i) const {
        return is64 ? b64[2 * i] : b32[i];
    }
};

__device__ __forceinline__ void flush_seg(float* __restrict__ out, int seg,
                                          int lane, const float4& acc, int cnt) {
    float* p = out + (size_t)seg * D + lane * 4;
    atomicAdd(p + 0, acc.x);
    atomicAdd(p + 1, acc.y);
    atomicAdd(p + 2, acc.z);
    atomicAdd(p + 3, acc.w);
    if (lane == 0) atomicAdd(&g_counts[seg], cnt);
}

__global__ void __launch_bounds__(256, 6) k_accum(const float4* __restrict__ x4,
                                                  const void* __restrict__ batch,
                                                  float* __restrict__ out, int n) {
    const int lane = threadIdx.x & 31;
    const int wid = (blockIdx.x << 3) + (threadIdx.x >> 5);
    const int tw = gridDim.x << 3;
    const int per = (n + tw - 1) / tw;
    int r0 = wid * per;
    int r1 = min(r0 + per, n);
    if (r0 >= r1) return;

    BatchReader br;
    br.b32 = (const int*)batch;
    br.b64 = (const int*)batch;
    br.is64 = g_is64;

    float4 acc = make_float4(0.f, 0.f, 0.f, 0.f);
    int cur = br.get(r0);
    int cnt = 0;

    int r = r0;
    // 4 rows per iteration; all 4 float4 loads issued before the boundary
    // branch (streaming hint: no reuse of x).
    for (; r + 4 <= r1; r += 4) {
        const float4* p = x4 + (size_t)r * 32 + lane;
        float4 v0 = __ldcs(p);
        float4 v1 = __ldcs(p + 32);
        float4 v2 = __ldcs(p + 64);
        float4 v3 = __ldcs(p + 96);
        int blast = br.get(r + 3);
        if (blast == cur) {
            acc.x += v0.x + v1.x + v2.x + v3.x;
            acc.y += v0.y + v1.y + v2.y + v3.y;
            acc.z += v0.z + v1.z + v2.z + v3.z;
            acc.w += v0.w + v1.w + v2.w + v3.w;
            cnt += 4;
        } else {
            float4 v[4] = {v0, v1, v2, v3};
#pragma unroll
            for (int k = 0; k < 4; k++) {
                int b = br.get(r + k);
                if (b != cur) {
                    flush_seg(out, cur, lane, acc, cnt);
                    acc = make_float4(0.f, 0.f, 0.f, 0.f);
                    cnt = 0;
                    cur = b;
                }
                acc.x += v[k].x; acc.y += v[k].y;
                acc.z += v[k].z; acc.w += v[k].w;
                cnt++;
            }
        }
    }
    // Tail rows
    for (; r < r1; r++) {
        int b = br.get(r);
        if (b != cur) {
            flush_seg(out, cur, lane, acc, cnt);
            acc = make_float4(0.f, 0.f, 0.f, 0.f);
            cnt = 0;
            cur = b;
        }
        float4 v = __ldcs(x4 + (size_t)r * 32 + lane);
        acc.x += v.x; acc.y += v.y; acc.z += v.z; acc.w += v.w;
        cnt++;
    }
    flush_seg(out, cur, lane, acc, cnt);
}

__global__ void k_div(float* __restrict__ out, int out_size) {
    int i = blockIdx.x * blockDim.x + threadIdx.x;
    if (i >= out_size) return;
    int seg = i >> 7;  // / D
    float c = (float)g_counts[seg];
    out[i] = out[i] / fmaxf(c, 1.0f);
}

extern "C" void kernel_launch(void* const* d_in, const int* in_sizes, int n_in,
                              void* d_out, int out_size) {
    const float* x = (const float*)d_in[0];
    const void* batch = d_in[1];

    int n = in_sizes[0] / D;               // number of rows
    int nb = out_size / D;                 // number of segments
    if (nb > MAXB) nb = MAXB;
    float* out = (float*)d_out;

    int zmax = out_size > nb ? out_size : nb;
    k_prep<<<(zmax + 255) / 256, 256>>>(out, out_size, nb,
                                        (const unsigned int*)batch, n);
    k_accum<<<888, 256>>>((const float4*)x, batch, out, n);
    k_div<<<(out_size + 255) / 256, 256>>>(out, out_size);
}

// round 4
// speedup vs baseline: 1.1807x; 1.0236x over previous
#include <cuda_runtime.h>

// ---------------------------------------------------------------------------
// MeanPooling: out[b,:] = mean of x[i,:] over rows i with batch[i]==b
// x: (N,128) fp32, batch: (N,) sorted int64-or-int32, out: (4096,128) fp32
// R3: 2 graph nodes. Sums go to __device__ scratch g_sums, which k_div
// re-zeroes after use (BSS starts zero -> every replay sees zero scratch).
// Batch dtype detection is done per-warp inside k_accum (L2-broadcast reads).
// ---------------------------------------------------------------------------

#define D 128
#define MAXB 8192
#define MAXOUT (MAXB * D)

__device__ float g_sums[MAXOUT];  // accumulation scratch; zero before+after
__device__ int g_counts[MAXB];    // per-segment row counts; zero before+after

// Detect dtype of batch buffer. Reads only within the first n 32-bit words
// (in-bounds for both layouts). int64 LE: odd words are high halves == 0
// (values < 4096). int32 sorted data: tail words ~ num_graphs-1 (nonzero).
__device__ __forceinline__ int detect_is64(const unsigned int* __restrict__ w,
                                           int n) {
    int top = n - 1;
    if ((top & 1) == 0) top--;          // largest odd index <= n-1
    int nz = 0;
#pragma unroll 1
    for (int k = 0; k < 32; k++) {
        int idx = top - 2 * k;
        if (idx < 1) break;
        if (w[idx] != 0u) { nz = 1; break; }
    }
    return (nz == 0) ? 1 : 0;
}

__device__ __forceinline__ void flush_seg(int seg, int lane,
                                          const float4& acc, int cnt) {
    float* p = g_sums + (size_t)seg * D + lane * 4;
    atomicAdd(p + 0, acc.x);
    atomicAdd(p + 1, acc.y);
    atomicAdd(p + 2, acc.z);
    atomicAdd(p + 3, acc.w);
    if (lane == 0) atomicAdd(&g_counts[seg], cnt);
}

__global__ void __launch_bounds__(256, 6) k_accum(const float4* __restrict__ x4,
                                                  const void* __restrict__ batch,
                                                  int n) {
    const int lane = threadIdx.x & 31;
    const int wid = (blockIdx.x << 3) + (threadIdx.x >> 5);
    const int tw = gridDim.x << 3;
    const int per = (n + tw - 1) / tw;
    int r0 = wid * per;
    int r1 = min(r0 + per, n);
    if (r0 >= r1) return;

    const int is64 = detect_is64((const unsigned int*)batch, n);
    const int* bw = (const int*)batch;
    // index helper: int32 -> bw[i], int64 LE -> low word at bw[2i]
    const int ish = is64 ? 1 : 0;

    float4 acc = make_float4(0.f, 0.f, 0.f, 0.f);
    int cur = bw[r0 << ish];
    int cnt = 0;

    int r = r0;
    // 4 rows per iteration; all 4 float4 loads issued before the boundary
    // branch (streaming hint: x has no reuse).
    for (; r + 4 <= r1; r += 4) {
        const float4* p = x4 + (size_t)r * 32 + lane;
        float4 v0 = __ldcs(p);
        float4 v1 = __ldcs(p + 32);
        float4 v2 = __ldcs(p + 64);
        float4 v3 = __ldcs(p + 96);
        int blast = bw[(r + 3) << ish];
        if (blast == cur) {
            acc.x += v0.x + v1.x + v2.x + v3.x;
            acc.y += v0.y + v1.y + v2.y + v3.y;
            acc.z += v0.z + v1.z + v2.z + v3.z;
            acc.w += v0.w + v1.w + v2.w + v3.w;
            cnt += 4;
        } else {
            float4 v[4] = {v0, v1, v2, v3};
#pragma unroll
            for (int k = 0; k < 4; k++) {
                int b = bw[(r + k) << ish];
                if (b != cur) {
                    flush_seg(cur, lane, acc, cnt);
                    acc = make_float4(0.f, 0.f, 0.f, 0.f);
                    cnt = 0;
                    cur = b;
                }
                acc.x += v[k].x; acc.y += v[k].y;
                acc.z += v[k].z; acc.w += v[k].w;
                cnt++;
            }
        }
    }
    // Tail rows
    for (; r < r1; r++) {
        int b = bw[r << ish];
        if (b != cur) {
            flush_seg(cur, lane, acc, cnt);
            acc = make_float4(0.f, 0.f, 0.f, 0.f);
            cnt = 0;
            cur = b;
        }
        float4 v = __ldcs(x4 + (size_t)r * 32 + lane);
        acc.x += v.x; acc.y += v.y; acc.z += v.z; acc.w += v.w;
        cnt++;
    }
    flush_seg(cur, lane, acc, cnt);
}

// Finalize: out = sums / max(count,1), then re-zero scratch so the next
// graph replay starts from a clean state (deterministic across replays).
__global__ void k_div(float* __restrict__ out, int out_size) {
    int i = blockIdx.x * blockDim.x + threadIdx.x;
    if (i >= out_size) return;
    int seg = i >> 7;  // / D
    float c = (float)g_counts[seg];
    out[i] = g_sums[i] / fmaxf(c, 1.0f);
    g_sums[i] = 0.0f;
    if ((i & (D - 1)) == 0) g_counts[seg] = 0;
}

extern "C" void kernel_launch(void* const* d_in, const int* in_sizes, int n_in,
                              void* d_out, int out_size) {
    const float* x = (const float*)d_in[0];
    const void* batch = d_in[1];

    int n = in_sizes[0] / D;               // number of rows
    float* out = (float*)d_out;

    k_accum<<<888, 256>>>((const float4*)x, batch, n);
    k_div<<<(out_size + 255) / 256, 256>>>(out, out_size);
}

// round 5
// speedup vs baseline: 1.1931x; 1.0104x over previous
#include <cuda_runtime.h>

// ---------------------------------------------------------------------------
// MeanPooling: out[b,:] = mean of x[i,:] over rows i with batch[i]==b
// x: (N,128) fp32, batch: (N,) sorted int64-or-int32, out: (4096,128) fp32
// R4: 2 graph nodes. k_div vectorized (float4/thread) to kill its latency
// bound; scratch g_sums/g_counts re-zeroed in k_div (BSS starts zero ->
// every graph replay sees clean scratch).
// ---------------------------------------------------------------------------

#define D 128
#define MAXB 8192
#define MAXOUT (MAXB * D)

__device__ float g_sums[MAXOUT];  // accumulation scratch; zero before+after
__device__ int g_counts[MAXB];    // per-segment row counts; zero before+after

// Detect dtype of batch buffer. Reads only within the first n 32-bit words
// (in-bounds for both layouts). int64 LE: odd words are high halves == 0
// (values < 4096). int32 sorted data: tail words ~ num_graphs-1 (nonzero).
__device__ __forceinline__ int detect_is64(const unsigned int* __restrict__ w,
                                           int n) {
    int top = n - 1;
    if ((top & 1) == 0) top--;          // largest odd index <= n-1
    int nz = 0;
#pragma unroll 1
    for (int k = 0; k < 32; k++) {
        int idx = top - 2 * k;
        if (idx < 1) break;
        if (w[idx] != 0u) { nz = 1; break; }
    }
    return (nz == 0) ? 1 : 0;
}

__device__ __forceinline__ void flush_seg(int seg, int lane,
                                          const float4& acc, int cnt) {
    float* p = g_sums + (size_t)seg * D + lane * 4;
    atomicAdd(p + 0, acc.x);
    atomicAdd(p + 1, acc.y);
    atomicAdd(p + 2, acc.z);
    atomicAdd(p + 3, acc.w);
    if (lane == 0) atomicAdd(&g_counts[seg], cnt);
}

__global__ void __launch_bounds__(256, 6) k_accum(const float4* __restrict__ x4,
                                                  const void* __restrict__ batch,
                                                  int n) {
    const int lane = threadIdx.x & 31;
    const int wid = (blockIdx.x << 3) + (threadIdx.x >> 5);
    const int tw = gridDim.x << 3;
    const int per = (n + tw - 1) / tw;
    int r0 = wid * per;
    int r1 = min(r0 + per, n);
    if (r0 >= r1) return;

    const int is64 = detect_is64((const unsigned int*)batch, n);
    const int* bw = (const int*)batch;
    const int ish = is64 ? 1 : 0;   // int64 LE: low word at bw[2i]

    float4 acc = make_float4(0.f, 0.f, 0.f, 0.f);
    int cur = bw[r0 << ish];
    int cnt = 0;

    int r = r0;
    // 4 rows per iteration; all 4 float4 loads issued before the boundary
    // branch (streaming hint: x has no reuse).
    for (; r + 4 <= r1; r += 4) {
        const float4* p = x4 + (size_t)r * 32 + lane;
        float4 v0 = __ldcs(p);
        float4 v1 = __ldcs(p + 32);
        float4 v2 = __ldcs(p + 64);
        float4 v3 = __ldcs(p + 96);
        int blast = bw[(r + 3) << ish];
        if (blast == cur) {
            acc.x += v0.x + v1.x + v2.x + v3.x;
            acc.y += v0.y + v1.y + v2.y + v3.y;
            acc.z += v0.z + v1.z + v2.z + v3.z;
            acc.w += v0.w + v1.w + v2.w + v3.w;
            cnt += 4;
        } else {
            float4 v[4] = {v0, v1, v2, v3};
#pragma unroll
            for (int k = 0; k < 4; k++) {
                int b = bw[(r + k) << ish];
                if (b != cur) {
                    flush_seg(cur, lane, acc, cnt);
                    acc = make_float4(0.f, 0.f, 0.f, 0.f);
                    cnt = 0;
                    cur = b;
                }
                acc.x += v[k].x; acc.y += v[k].y;
                acc.z += v[k].z; acc.w += v[k].w;
                cnt++;
            }
        }
    }
    // Tail rows
    for (; r < r1; r++) {
        int b = bw[r << ish];
        if (b != cur) {
            flush_seg(cur, lane, acc, cnt);
            acc = make_float4(0.f, 0.f, 0.f, 0.f);
            cnt = 0;
            cur = b;
        }
        float4 v = __ldcs(x4 + (size_t)r * 32 + lane);
        acc.x += v.x; acc.y += v.y; acc.z += v.z; acc.w += v.w;
        cnt++;
    }
    flush_seg(cur, lane, acc, cnt);
}

// Finalize (vectorized): out4 = sums4 * (1/max(count,1)); re-zero scratch so
// the next graph replay starts clean. One float4 per thread; count is shared
// by 32 consecutive threads (D/4 = 32 float4 per segment row).
__global__ void __launch_bounds__(256) k_div(float4* __restrict__ out,
                                             int n4) {
    int i = blockIdx.x * blockDim.x + threadIdx.x;
    if (i >= n4) return;
    int seg = i >> 5;                    // (i*4) / 128
    float c = (float)g_counts[seg];
    float rinv = __frcp_rn(fmaxf(c, 1.0f));
    float4* s4 = (float4*)g_sums;
    float4 v = s4[i];
    v.x *= rinv; v.y *= rinv; v.z *= rinv; v.w *= rinv;
    out[i] = v;
    s4[i] = make_float4(0.f, 0.f, 0.f, 0.f);
    if ((i & 31) == 0) g_counts[seg] = 0;
}

extern "C" void kernel_launch(void* const* d_in, const int* in_sizes, int n_in,
                              void* d_out, int out_size) {
    const float* x = (const float*)d_in[0];
    const void* batch = d_in[1];

    int n = in_sizes[0] / D;               // number of rows
    int n4 = out_size / 4;                 // float4 elements in output

    k_accum<<<888, 256>>>((const float4*)x, batch, n);
    k_div<<<(n4 + 255) / 256, 256>>>((float4*)d_out, n4);
}